// round 2
// baseline (speedup 1.0000x reference)
#include <cuda_runtime.h>
#include <math.h>

// Problem constants
#define BI   4
#define LI   2048
#define DI   1024
#define HI   16
#define DKI  64

// Scratch (device globals: allocation-free per harness rules). ~201 MB total.
__device__ float g_Qh[(size_t)BI*HI*LI*DKI];   // [b][h][l][dk]
__device__ float g_Kh[(size_t)BI*HI*LI*DKI];   // [b][h][l][dk]
__device__ float g_Vh[(size_t)BI*HI*LI*DKI];   // [b][h][l][dv]
__device__ float g_Vt[(size_t)BI*HI*DKI*LI];   // [b][h][dv][l]  (transposed V)
__device__ float g_O [(size_t)BI*LI*DI];       // attn @ V, [b][l][h*dv]
__device__ float g_O2[(size_t)BI*LI*DI];       // out-proj result (pre-LN)

// ---------------- packed fp32x2 helpers (Blackwell f32x2 pipe) ----------------
__device__ __forceinline__ void fma2(unsigned long long& c, unsigned long long a,
                                     unsigned long long b) {
    asm("fma.rn.f32x2 %0, %1, %2, %3;" : "=l"(c) : "l"(a), "l"(b), "l"(c));
}
__device__ __forceinline__ unsigned long long rep2(float x) {
    unsigned long long r; unsigned u = __float_as_uint(x);
    asm("mov.b64 %0, {%1, %1};" : "=l"(r) : "r"(u));
    return r;
}
__device__ __forceinline__ void unpack2(unsigned long long c, float& lo, float& hi) {
    unsigned a, b;
    asm("mov.b64 {%0, %1}, %2;" : "=r"(a), "=r"(b) : "l"(c));
    lo = __uint_as_float(a); hi = __uint_as_float(b);
}

// ---------------------------------------------------------------------------
// Generic NT GEMM: C = A(MxK, row-major) * B(NxK, row-major)^T  [+ bias]
// MODE 0: QKV projection -> scatter to [b][h][l][dk], += bias[j]
// MODE 1: plain row-major C[M][N], += bias[j]
// MODE 2: scores (batched over z = b*H+h): val*scale, diag -> -inf,
//         written to attn_flat layout [h][b][l][m]
// MODE 3: attn@V (batched over z = b*H+h): write to g_O[b][l][h*64+dv]
// All dims assumed multiples of tile sizes (true for this problem).
// ---------------------------------------------------------------------------
template<int BM, int BN, int BK, int TM, int TN, int MODE>
__global__ void __launch_bounds__((BM/TM)*(BN/TN))
gemm_nt(const float* __restrict__ A, const float* __restrict__ B,
        float* __restrict__ C, const float* __restrict__ bias,
        int M, int N, int K, float scale)
{
    constexpr int NT = (BM/TM)*(BN/TN);
    __shared__ __align__(16) float As[BK][BM];
    __shared__ __align__(16) float Bs[BK][BN];

    const int tid = threadIdx.x;
    const int bc = blockIdx.x, br = blockIdx.y, z = blockIdx.z;

    const float* Ap = A;
    const float* Bp = B;
    if (MODE == 2) {
        Ap = A + (size_t)z * LI * DKI;          // Qh batch (b*H+h)
        Bp = B + (size_t)z * LI * DKI;          // Kh batch
    }
    if (MODE == 3) {
        int b = z / HI, h = z % HI;
        Ap = A + ((size_t)(h * BI + b)) * LI * LI;   // attn_flat [h][b]
        Bp = B + (size_t)z * DKI * LI;               // Vt batch
    }

    unsigned long long acc[TM][TN/2];
    #pragma unroll
    for (int i = 0; i < TM; i++)
        #pragma unroll
        for (int j = 0; j < TN/2; j++) acc[i][j] = 0ULL;

    const int trow = tid / (BN/TN);
    const int tcol = tid % (BN/TN);

    constexpr int AV4 = BM * BK / 4;
    constexpr int BV4 = BN * BK / 4;

    for (int k0 = 0; k0 < K; k0 += BK) {
        #pragma unroll
        for (int idx = tid; idx < AV4; idx += NT) {
            int r  = idx / (BK/4);
            int c4 = idx % (BK/4);
            float4 v = *(const float4*)(Ap + (size_t)(br*BM + r)*K + k0 + c4*4);
            As[c4*4+0][r] = v.x; As[c4*4+1][r] = v.y;
            As[c4*4+2][r] = v.z; As[c4*4+3][r] = v.w;
        }
        #pragma unroll
        for (int idx = tid; idx < BV4; idx += NT) {
            int r  = idx / (BK/4);
            int c4 = idx % (BK/4);
            float4 v = *(const float4*)(Bp + (size_t)(bc*BN + r)*K + k0 + c4*4);
            Bs[c4*4+0][r] = v.x; Bs[c4*4+1][r] = v.y;
            Bs[c4*4+2][r] = v.z; Bs[c4*4+3][r] = v.w;
        }
        __syncthreads();

        #pragma unroll
        for (int k = 0; k < BK; k++) {
            float a_frag[TM];
            #pragma unroll
            for (int i = 0; i < TM; i += 4) {
                float4 v = *(const float4*)&As[k][trow*TM + i];
                a_frag[i] = v.x; a_frag[i+1] = v.y; a_frag[i+2] = v.z; a_frag[i+3] = v.w;
            }
            unsigned long long b_frag[TN/2];
            #pragma unroll
            for (int j = 0; j < TN/2; j += 2) {
                ulonglong2 u = *(const ulonglong2*)&Bs[k][tcol*TN + j*2];
                b_frag[j] = u.x; b_frag[j+1] = u.y;
            }
            #pragma unroll
            for (int i = 0; i < TM; i++) {
                unsigned long long a2 = rep2(a_frag[i]);
                #pragma unroll
                for (int j = 0; j < TN/2; j++) fma2(acc[i][j], a2, b_frag[j]);
            }
        }
        __syncthreads();
    }

    // Epilogue
    #pragma unroll
    for (int i = 0; i < TM; i++) {
        int gi = br*BM + trow*TM + i;
        #pragma unroll
        for (int j = 0; j < TN/2; j++) {
            float lo, hi;
            unpack2(acc[i][j], lo, hi);
            int gj0 = bc*BN + tcol*TN + j*2;
            #pragma unroll
            for (int s = 0; s < 2; s++) {
                int gj = gj0 + s;
                float v = (s == 0) ? lo : hi;
                if (MODE == 0) {
                    int b = gi >> 11, l = gi & (LI-1);
                    int h = gj >> 6,  dk = gj & 63;
                    C[(((size_t)(b*HI + h)*LI + l) << 6) + dk] = v + bias[gj];
                } else if (MODE == 1) {
                    C[(size_t)gi * N + gj] = v + bias[gj];
                } else if (MODE == 2) {
                    int b = z / HI, h = z % HI;
                    float sv = v * scale;
                    if (gi == gj) sv = -INFINITY;
                    C[((size_t)(h*BI + b)*LI + gi)*LI + gj] = sv;
                } else { // MODE 3
                    int b = z / HI, h = z % HI;
                    C[((size_t)b*LI + gi)*DI + h*DKI + gj] = v;
                }
            }
        }
    }
}

// ---------------- V transpose: [b][h][l][dv] -> [b][h][dv][l] ----------------
__global__ void __launch_bounds__(256) transpose_v(const float* __restrict__ in,
                                                   float* __restrict__ out)
{
    __shared__ float t[32][33];
    int z  = blockIdx.z;                 // bh
    int l0 = blockIdx.y * 32;
    int d0 = blockIdx.x * 32;
    const float* ip = in  + (size_t)z * LI * DKI;
    float*       op = out + (size_t)z * DKI * LI;
    int x = threadIdx.x, y = threadIdx.y;   // 32 x 8
    #pragma unroll
    for (int i = 0; i < 32; i += 8)
        t[y + i][x] = ip[(size_t)(l0 + y + i) * DKI + d0 + x];
    __syncthreads();
    #pragma unroll
    for (int i = 0; i < 32; i += 8)
        op[(size_t)(d0 + y + i) * LI + l0 + x] = t[x][y + i];
}

// ---------------- reductions ----------------
__device__ __forceinline__ float warpMax(float v) {
    #pragma unroll
    for (int o = 16; o; o >>= 1) v = fmaxf(v, __shfl_xor_sync(0xffffffffu, v, o));
    return v;
}
__device__ __forceinline__ float warpSum(float v) {
    #pragma unroll
    for (int o = 16; o; o >>= 1) v += __shfl_xor_sync(0xffffffffu, v, o);
    return v;
}

// ---------------- row softmax in-place over attn [64*2048 rows x 2048] -------
__global__ void __launch_bounds__(256) softmax_kernel(float* __restrict__ attn)
{
    size_t row = blockIdx.x;
    float4* p = (float4*)(attn + row * LI);
    int t = threadIdx.x;
    float4 v0 = p[t];
    float4 v1 = p[t + 256];

    float m = fmaxf(fmaxf(fmaxf(v0.x, v0.y), fmaxf(v0.z, v0.w)),
                    fmaxf(fmaxf(v1.x, v1.y), fmaxf(v1.z, v1.w)));
    m = warpMax(m);
    __shared__ float red[8];
    if ((t & 31) == 0) red[t >> 5] = m;
    __syncthreads();
    m = red[0];
    #pragma unroll
    for (int i = 1; i < 8; i++) m = fmaxf(m, red[i]);

    v0.x = __expf(v0.x - m); v0.y = __expf(v0.y - m);
    v0.z = __expf(v0.z - m); v0.w = __expf(v0.w - m);
    v1.x = __expf(v1.x - m); v1.y = __expf(v1.y - m);
    v1.z = __expf(v1.z - m); v1.w = __expf(v1.w - m);

    float s = (v0.x + v0.y + v0.z + v0.w) + (v1.x + v1.y + v1.z + v1.w);
    s = warpSum(s);
    __syncthreads();
    if ((t & 31) == 0) red[t >> 5] = s;
    __syncthreads();
    s = red[0];
    #pragma unroll
    for (int i = 1; i < 8; i++) s += red[i];

    float inv = 1.0f / s;
    v0.x *= inv; v0.y *= inv; v0.z *= inv; v0.w *= inv;
    v1.x *= inv; v1.y *= inv; v1.z *= inv; v1.w *= inv;
    p[t] = v0;
    p[t + 256] = v1;
}

// ---------------- residual + LayerNorm (biased variance) ---------------------
__global__ void __launch_bounds__(256) ln_kernel(const float* __restrict__ o2,
                                                 const float* __restrict__ res,
                                                 const float* __restrict__ gamma,
                                                 const float* __restrict__ beta,
                                                 float* __restrict__ out)
{
    size_t row = blockIdx.x;
    int t = threadIdx.x;
    float4 a = ((const float4*)(o2  + row * DI))[t];
    float4 r = ((const float4*)(res + row * DI))[t];
    float x0 = a.x + r.x, x1 = a.y + r.y, x2 = a.z + r.z, x3 = a.w + r.w;
    float s  = x0 + x1 + x2 + x3;
    float sq = x0*x0 + x1*x1 + x2*x2 + x3*x3;
    s = warpSum(s); sq = warpSum(sq);
    __shared__ float rs[8], rq[8];
    if ((t & 31) == 0) { rs[t >> 5] = s; rq[t >> 5] = sq; }
    __syncthreads();
    s = 0.0f; sq = 0.0f;
    #pragma unroll
    for (int i = 0; i < 8; i++) { s += rs[i]; sq += rq[i]; }
    float mu   = s * (1.0f / DI);
    float var  = sq * (1.0f / DI) - mu * mu;
    float rstd = rsqrtf(var + 1e-5f);
    float4 g = ((const float4*)gamma)[t];
    float4 b = ((const float4*)beta)[t];
    float4 o;
    o.x = (x0 - mu) * rstd * g.x + b.x;
    o.y = (x1 - mu) * rstd * g.y + b.y;
    o.z = (x2 - mu) * rstd * g.z + b.z;
    o.w = (x3 - mu) * rstd * g.w + b.w;
    ((float4*)(out + row * DI))[t] = o;
}

// ---------------------------------------------------------------------------
extern "C" void kernel_launch(void* const* d_in, const int* in_sizes, int n_in,
                              void* d_out, int out_size)
{
    const float* q     = (const float*)d_in[0];
    const float* k     = (const float*)d_in[1];
    const float* v     = (const float*)d_in[2];
    const float* Wq    = (const float*)d_in[3];
    const float* bq    = (const float*)d_in[4];
    const float* Wk    = (const float*)d_in[5];
    const float* bk    = (const float*)d_in[6];
    const float* Wv    = (const float*)d_in[7];
    const float* bv    = (const float*)d_in[8];
    const float* Wo    = (const float*)d_in[9];
    const float* bo    = (const float*)d_in[10];
    const float* gamma = (const float*)d_in[11];
    const float* beta  = (const float*)d_in[12];

    float* out  = (float*)d_out;
    float* attn = out + (size_t)BI * LI * DI;   // attn_flat [h*B][L][L]

    float *pQh, *pKh, *pVh, *pVt, *pO, *pO2;
    cudaGetSymbolAddress((void**)&pQh, g_Qh);
    cudaGetSymbolAddress((void**)&pKh, g_Kh);
    cudaGetSymbolAddress((void**)&pVh, g_Vh);
    cudaGetSymbolAddress((void**)&pVt, g_Vt);
    cudaGetSymbolAddress((void**)&pO,  g_O);
    cudaGetSymbolAddress((void**)&pO2, g_O2);

    const int M = BI * LI;   // 8192

    // QKV projections -> [b][h][l][d]
    gemm_nt<128,128,16,8,8,0><<<dim3(DI/128, M/128, 1), 256>>>(q, Wq, pQh, bq, M, DI, DI, 0.f);
    gemm_nt<128,128,16,8,8,0><<<dim3(DI/128, M/128, 1), 256>>>(k, Wk, pKh, bk, M, DI, DI, 0.f);
    gemm_nt<128,128,16,8,8,0><<<dim3(DI/128, M/128, 1), 256>>>(v, Wv, pVh, bv, M, DI, DI, 0.f);

    // V transpose for NT attn@V
    transpose_v<<<dim3(DKI/32, LI/32, BI*HI), dim3(32, 8)>>>(pVh, pVt);

    // scores = scale * Q Kt, diag -> -inf, written to attn_flat layout
    gemm_nt<128,128,16,8,8,2><<<dim3(LI/128, LI/128, BI*HI), 256>>>(pQh, pKh, attn, nullptr,
                                                                    LI, LI, DKI, 0.125f);
    // row softmax in place
    softmax_kernel<<<BI*HI*LI, 256>>>(attn);

    // attn @ V -> g_O [b][l][h*dv]
    gemm_nt<128,64,16,8,8,3><<<dim3(1, LI/128, BI*HI), 128>>>(attn, pVt, pO, nullptr,
                                                              LI, DKI, LI, 0.f);
    // output projection
    gemm_nt<128,128,16,8,8,1><<<dim3(DI/128, M/128, 1), 256>>>(pO, Wo, pO2, bo, M, DI, DI, 0.f);

    // residual + LayerNorm -> out
    ln_kernel<<<M, 256>>>(pO2, q, gamma, beta, out);
}

// round 4
// speedup vs baseline: 2.2614x; 2.2614x over previous
#include <cuda_runtime.h>
#include <cuda_bf16.h>
#include <cstdint>
#include <math.h>

#define BI 4
#define LI 2048
#define DI 1024
#define HI 16

typedef __nv_bfloat16 bf16;
#define ELI ((size_t)8192*1024)
#define ELW ((size_t)1024*1024)

// device-global scratch (allocation-free rule)
__device__ __align__(256) bf16 g_qhi[ELI], g_qlo[ELI], g_khi[ELI], g_klo[ELI], g_vhi[ELI], g_vlo[ELI];
__device__ __align__(256) bf16 g_wqhi[ELW], g_wqlo[ELW], g_wkhi[ELW], g_wklo[ELW];
__device__ __align__(256) bf16 g_wvhi[ELW], g_wvlo[ELW], g_wohi[ELW], g_wolo[ELW];
__device__ __align__(256) bf16 g_Qhi[ELI], g_Qlo[ELI], g_Khi[ELI], g_Klo[ELI];   // [bh][l][64]
__device__ __align__(256) bf16 g_VHhi[ELI], g_VHlo[ELI];                         // [bh][l][64]
__device__ __align__(256) bf16 g_Vthi[ELI], g_Vtlo[ELI];                         // [bh][64][2048]
__device__ __align__(256) bf16 g_Ohi[ELI], g_Olo[ELI];                           // [8192][1024]
__device__ __align__(256) float g_O2[ELI];

// ---------------- helpers ----------------
__device__ __forceinline__ uint32_t s2u(const void* p) {
    uint32_t a;
    asm("{ .reg .u64 t; cvta.to.shared.u64 t, %1; cvt.u32.u64 %0, t; }" : "=r"(a) : "l"(p));
    return a;
}
__device__ __forceinline__ void ldm4(uint32_t* r, uint32_t a) {
    asm volatile("ldmatrix.sync.aligned.m8n8.x4.shared.b16 {%0,%1,%2,%3}, [%4];"
                 : "=r"(r[0]), "=r"(r[1]), "=r"(r[2]), "=r"(r[3]) : "r"(a));
}
__device__ __forceinline__ void mma16816(float* c, const uint32_t* a, const uint32_t* b) {
    asm volatile("mma.sync.aligned.m16n8k16.row.col.f32.bf16.bf16.f32 "
                 "{%0,%1,%2,%3}, {%4,%5,%6,%7}, {%8,%9}, {%0,%1,%2,%3};"
                 : "+f"(c[0]), "+f"(c[1]), "+f"(c[2]), "+f"(c[3])
                 : "r"(a[0]), "r"(a[1]), "r"(a[2]), "r"(a[3]), "r"(b[0]), "r"(b[1]));
}
__device__ __forceinline__ void split2(float x0, float x1, unsigned& H, unsigned& L) {
    bf16 h0 = __float2bfloat16(x0), h1 = __float2bfloat16(x1);
    bf16 l0 = __float2bfloat16(x0 - __bfloat162float(h0));
    bf16 l1 = __float2bfloat16(x1 - __bfloat162float(h1));
    H = (unsigned)__bfloat16_as_ushort(h0) | ((unsigned)__bfloat16_as_ushort(h1) << 16);
    L = (unsigned)__bfloat16_as_ushort(l0) | ((unsigned)__bfloat16_as_ushort(l1) << 16);
}
__global__ void __launch_bounds__(256) convert_split(const float* __restrict__ s,
                                                     bf16* __restrict__ hi, bf16* __restrict__ lo, int n4) {
    int i = blockIdx.x * 256 + threadIdx.x;
    if (i >= n4) return;
    float4 v = ((const float4*)s)[i];
    unsigned h01, l01, h23, l23;
    split2(v.x, v.y, h01, l01); split2(v.z, v.w, h23, l23);
    ((uint2*)hi)[i] = make_uint2(h01, h23);
    ((uint2*)lo)[i] = make_uint2(l01, l23);
}

// ---------------------------------------------------------------------------
// mma.sync split-bf16 GEMM: C = A(MxK,row) * B(NxK,row)^T, CTA tile 128 x BN
// MODE 0: QKV proj -> Chi/Clo scatter [bh][l][64], +bias
// MODE 1: out proj -> Cf [8192][1024], +bias
// MODE 2: scores   -> Cf attn [(h*4+b)][gi][gj], *0.125, diag=-inf (K=64)
// MODE 3: attn@V   -> A = fp32 attn (split on load); Chi/Clo [8192][1024]
// ---------------------------------------------------------------------------
template<int BN, int MODE>
__global__ void __launch_bounds__(256)
gemm_mma(const bf16* __restrict__ Ahi, const bf16* __restrict__ Alo, const float* __restrict__ Af,
         const bf16* __restrict__ Bhi, const bf16* __restrict__ Blo,
         float* __restrict__ Cf, bf16* __restrict__ Chi, bf16* __restrict__ Clo,
         const float* __restrict__ bias, int K)
{
    constexpr int BM = 128, BK = 32, BKP = 40;
    constexpr int ASZ = BM * BKP * 2;            // bytes per A plane
    constexpr int BSZ = BN * BKP * 2;
    constexpr int STAGE = 2 * ASZ + 2 * BSZ;
    constexpr int NF = BN / 16;                  // n-frags per warp (warp covers BN/2 cols)
    constexpr int BV = BN / 64;                  // B uint4 ldg per thread per plane

    extern __shared__ char smem[];
    const uint32_t sbase = s2u(smem);

    const int t = threadIdx.x, l = t & 31, wid = t >> 5;
    const int wm = wid & 3, wn = wid >> 2;
    const int bc = blockIdx.x, br = blockIdx.y, z = blockIdx.z;

    const bf16 *Ah = Ahi, *Al = Alo, *Bh = Bhi, *Bl = Blo;
    const float* Afp = Af;
    if (MODE == 2) { size_t o = (size_t)z * LI * 64; Ah += o; Al += o; Bh += o; Bl += o; }
    if (MODE == 3) {
        Afp = Af + ((size_t)((z & 15) * BI + (z >> 4))) * LI * LI;
        size_t o = (size_t)z * 64 * LI; Bh += o; Bl += o;
    }

    // per-thread fragment smem byte offsets (relative to stage base)
    int aoff[2], boff[NF / 2];
    #pragma unroll
    for (int mi = 0; mi < 2; mi++)
        aoff[mi] = ((wm * 32 + mi * 16 + (l & 15)) * BKP + ((l & 16) >> 1)) * 2;
    #pragma unroll
    for (int p = 0; p < NF / 2; p++)
        boff[p] = ((wn * (BN / 2) + p * 16 + (l & 7) + ((l >> 1) & 8)) * BKP + (l & 8)) * 2;

    float acc[2][NF][4];
    #pragma unroll
    for (int mi = 0; mi < 2; mi++)
        #pragma unroll
        for (int ni = 0; ni < NF; ni++)
            #pragma unroll
            for (int c = 0; c < 4; c++) acc[mi][ni][c] = 0.f;

    // ldg staging registers
    uint4 ra_h[2], ra_l[2], rb_h[BV ? BV : 1], rb_l[BV ? BV : 1];
    float4 raf[4];

    const int n = K / BK;

    // ---- ldg(ck) ----
    auto ldg = [&](int ck) {
        int k0 = ck * BK;
        if (MODE == 3) {
            #pragma unroll
            for (int i = 0; i < 4; i++) {
                int vi = t + i * 256, row = vi >> 3, kc = (vi & 7) * 4;
                raf[i] = *(const float4*)(Afp + (size_t)(br * 128 + row) * K + k0 + kc);
            }
        } else {
            #pragma unroll
            for (int i = 0; i < 2; i++) {
                int vi = t + i * 256, row = vi >> 2, kc = (vi & 3) * 8;
                size_t g = (size_t)(br * 128 + row) * K + k0 + kc;
                ra_h[i] = *(const uint4*)(Ah + g);
                ra_l[i] = *(const uint4*)(Al + g);
            }
        }
        #pragma unroll
        for (int i = 0; i < BV; i++) {
            int vi = t + i * 256, row = vi >> 2, kc = (vi & 3) * 8;
            size_t g = (size_t)(bc * BN + row) * K + k0 + kc;
            rb_h[i] = *(const uint4*)(Bh + g);
            rb_l[i] = *(const uint4*)(Bl + g);
        }
    };
    // ---- sts(buf) ----
    auto sts = [&](int buf) {
        char* st = smem + buf * STAGE;
        if (MODE == 3) {
            #pragma unroll
            for (int i = 0; i < 4; i++) {
                int vi = t + i * 256, row = vi >> 3, kc = (vi & 7) * 4;
                unsigned h01, l01, h23, l23;
                split2(raf[i].x, raf[i].y, h01, l01);
                split2(raf[i].z, raf[i].w, h23, l23);
                *(uint2*)(st + (row * BKP + kc) * 2)       = make_uint2(h01, h23);
                *(uint2*)(st + ASZ + (row * BKP + kc) * 2) = make_uint2(l01, l23);
            }
        } else {
            #pragma unroll
            for (int i = 0; i < 2; i++) {
                int vi = t + i * 256, row = vi >> 2, kc = (vi & 3) * 8;
                *(uint4*)(st + (row * BKP + kc) * 2)       = ra_h[i];
                *(uint4*)(st + ASZ + (row * BKP + kc) * 2) = ra_l[i];
            }
        }
        #pragma unroll
        for (int i = 0; i < BV; i++) {
            int vi = t + i * 256, row = vi >> 2, kc = (vi & 3) * 8;
            *(uint4*)(st + 2 * ASZ + (row * BKP + kc) * 2)       = rb_h[i];
            *(uint4*)(st + 2 * ASZ + BSZ + (row * BKP + kc) * 2) = rb_l[i];
        }
    };
    // ---- compute(buf) ----
    auto compute = [&](int buf) {
        uint32_t sb = sbase + buf * STAGE;
        #pragma unroll
        for (int ks = 0; ks < 2; ks++) {
            int kb = ks * 32;   // 16 elements * 2B
            uint32_t ah[2][4], al[2][4];
            #pragma unroll
            for (int mi = 0; mi < 2; mi++) {
                ldm4(ah[mi], sb + aoff[mi] + kb);
                ldm4(al[mi], sb + ASZ + aoff[mi] + kb);
            }
            uint32_t bh[NF][2], bl[NF][2];
            #pragma unroll
            for (int p = 0; p < NF / 2; p++) {
                uint32_t r[4];
                ldm4(r, sb + 2 * ASZ + boff[p] + kb);
                bh[2*p][0] = r[0]; bh[2*p][1] = r[1]; bh[2*p+1][0] = r[2]; bh[2*p+1][1] = r[3];
                ldm4(r, sb + 2 * ASZ + BSZ + boff[p] + kb);
                bl[2*p][0] = r[0]; bl[2*p][1] = r[1]; bl[2*p+1][0] = r[2]; bl[2*p+1][1] = r[3];
            }
            #pragma unroll
            for (int mi = 0; mi < 2; mi++)
                #pragma unroll
                for (int ni = 0; ni < NF; ni++) {
                    mma16816(acc[mi][ni], ah[mi], bh[ni]);
                    mma16816(acc[mi][ni], ah[mi], bl[ni]);
                    mma16816(acc[mi][ni], al[mi], bh[ni]);
                }
        }
    };

    // pipeline
    ldg(0); sts(0); __syncthreads();
    for (int ck = 0; ck < n; ck++) {
        int buf = ck & 1;
        if (ck + 1 < n) ldg(ck + 1);
        compute(buf);
        if (ck + 1 < n) { sts(buf ^ 1); __syncthreads(); }
    }

    // ---- epilogue ----
    const int gid = l >> 2, tig = l & 3;
    #pragma unroll
    for (int mi = 0; mi < 2; mi++)
        #pragma unroll
        for (int ni = 0; ni < NF; ni++)
            #pragma unroll
            for (int h = 0; h < 2; h++) {
                int gi = br * 128 + wm * 32 + mi * 16 + gid + h * 8;
                int gj = bc * BN + wn * (BN / 2) + ni * 8 + tig * 2;
                float v0 = acc[mi][ni][h * 2 + 0];
                float v1 = acc[mi][ni][h * 2 + 1];
                if (MODE == 1) {
                    v0 += bias[gj]; v1 += bias[gj + 1];
                    *(float2*)&Cf[(size_t)gi * DI + gj] = make_float2(v0, v1);
                } else if (MODE == 0) {
                    v0 += bias[gj]; v1 += bias[gj + 1];
                    unsigned H, L;
                    split2(v0, v1, H, L);
                    size_t e = (((size_t)((gi >> 11) * HI + (gj >> 6)) * LI + (gi & 2047)) << 6) + (gj & 63);
                    ((unsigned*)Chi)[e >> 1] = H;
                    ((unsigned*)Clo)[e >> 1] = L;
                } else if (MODE == 2) {
                    v0 *= 0.125f; v1 *= 0.125f;
                    if (gi == gj)     v0 = -INFINITY;
                    if (gi == gj + 1) v1 = -INFINITY;
                    int b = z >> 4, hh = z & 15;
                    *(float2*)&Cf[((size_t)(hh * BI + b) * LI + gi) * LI + gj] = make_float2(v0, v1);
                } else { // MODE 3
                    unsigned H, L;
                    split2(v0, v1, H, L);
                    size_t e = ((size_t)(z >> 4) * LI + gi) * DI + (z & 15) * 64 + gj;
                    ((unsigned*)Chi)[e >> 1] = H;
                    ((unsigned*)Clo)[e >> 1] = L;
                }
            }
}

// ---------------- V transpose (hi+lo): [bh][l][64] -> [bh][64][2048] ----------
__global__ void __launch_bounds__(256) transpose_bf(const bf16* __restrict__ ih, const bf16* __restrict__ il,
                                                    bf16* __restrict__ oh, bf16* __restrict__ ol) {
    __shared__ bf16 th[32][33], tl[32][33];
    int z = blockIdx.z, l0 = blockIdx.y * 32, d0 = blockIdx.x * 32;
    int x = threadIdx.x, y = threadIdx.y;
    #pragma unroll
    for (int i = 0; i < 32; i += 8) {
        size_t g = ((size_t)z * LI + l0 + y + i) * 64 + d0 + x;
        th[y + i][x] = ih[g]; tl[y + i][x] = il[g];
    }
    __syncthreads();
    #pragma unroll
    for (int i = 0; i < 32; i += 8) {
        size_t g = ((size_t)z * 64 + d0 + y + i) * LI + l0 + x;
        oh[g] = th[x][y + i]; ol[g] = tl[x][y + i];
    }
}

// ---------------- reductions / softmax / LN ----------------
__device__ __forceinline__ float warpMax(float v) {
    #pragma unroll
    for (int o = 16; o; o >>= 1) v = fmaxf(v, __shfl_xor_sync(0xffffffffu, v, o));
    return v;
}
__device__ __forceinline__ float warpSum(float v) {
    #pragma unroll
    for (int o = 16; o; o >>= 1) v += __shfl_xor_sync(0xffffffffu, v, o);
    return v;
}
__global__ void __launch_bounds__(256) softmax_kernel(float* __restrict__ attn) {
    size_t row = blockIdx.x;
    float4* p = (float4*)(attn + row * LI);
    int t = threadIdx.x;
    float4 v0 = p[t], v1 = p[t + 256];
    float m = fmaxf(fmaxf(fmaxf(v0.x, v0.y), fmaxf(v0.z, v0.w)),
                    fmaxf(fmaxf(v1.x, v1.y), fmaxf(v1.z, v1.w)));
    m = warpMax(m);
    __shared__ float red[8];
    if ((t & 31) == 0) red[t >> 5] = m;
    __syncthreads();
    m = red[0];
    #pragma unroll
    for (int i = 1; i < 8; i++) m = fmaxf(m, red[i]);
    v0.x = __expf(v0.x - m); v0.y = __expf(v0.y - m); v0.z = __expf(v0.z - m); v0.w = __expf(v0.w - m);
    v1.x = __expf(v1.x - m); v1.y = __expf(v1.y - m); v1.z = __expf(v1.z - m); v1.w = __expf(v1.w - m);
    float s = (v0.x + v0.y + v0.z + v0.w) + (v1.x + v1.y + v1.z + v1.w);
    s = warpSum(s);
    __syncthreads();
    if ((t & 31) == 0) red[t >> 5] = s;
    __syncthreads();
    s = red[0];
    #pragma unroll
    for (int i = 1; i < 8; i++) s += red[i];
    float inv = 1.0f / s;
    v0.x *= inv; v0.y *= inv; v0.z *= inv; v0.w *= inv;
    v1.x *= inv; v1.y *= inv; v1.z *= inv; v1.w *= inv;
    p[t] = v0; p[t + 256] = v1;
}
__global__ void __launch_bounds__(256) ln_kernel(const float* __restrict__ o2, const float* __restrict__ res,
                                                 const float* __restrict__ gamma, const float* __restrict__ beta,
                                                 float* __restrict__ out) {
    size_t row = blockIdx.x;
    int t = threadIdx.x;
    float4 a = ((const float4*)(o2 + row * DI))[t];
    float4 r = ((const float4*)(res + row * DI))[t];
    float x0 = a.x + r.x, x1 = a.y + r.y, x2 = a.z + r.z, x3 = a.w + r.w;
    float s = x0 + x1 + x2 + x3, sq = x0 * x0 + x1 * x1 + x2 * x2 + x3 * x3;
    s = warpSum(s); sq = warpSum(sq);
    __shared__ float rs[8], rq[8];
    if ((t & 31) == 0) { rs[t >> 5] = s; rq[t >> 5] = sq; }
    __syncthreads();
    s = 0.f; sq = 0.f;
    #pragma unroll
    for (int i = 0; i < 8; i++) { s += rs[i]; sq += rq[i]; }
    float mu = s * (1.0f / DI);
    float rstd = rsqrtf(sq * (1.0f / DI) - mu * mu + 1e-5f);
    float4 g = ((const float4*)gamma)[t], b = ((const float4*)beta)[t];
    float4 o;
    o.x = (x0 - mu) * rstd * g.x + b.x; o.y = (x1 - mu) * rstd * g.y + b.y;
    o.z = (x2 - mu) * rstd * g.z + b.z; o.w = (x3 - mu) * rstd * g.w + b.w;
    ((float4*)(out + row * DI))[t] = o;
}

// ---------------------------------------------------------------------------
extern "C" void kernel_launch(void* const* d_in, const int* in_sizes, int n_in,
                              void* d_out, int out_size)
{
    const float* q  = (const float*)d_in[0];
    const float* k  = (const float*)d_in[1];
    const float* v  = (const float*)d_in[2];
    const float* Wq = (const float*)d_in[3];  const float* bq = (const float*)d_in[4];
    const float* Wk = (const float*)d_in[5];  const float* bk = (const float*)d_in[6];
    const float* Wv = (const float*)d_in[7];  const float* bv = (const float*)d_in[8];
    const float* Wo = (const float*)d_in[9];  const float* bo = (const float*)d_in[10];
    const float* gamma = (const float*)d_in[11];
    const float* beta  = (const float*)d_in[12];

    float* out  = (float*)d_out;
    float* attn = out + (size_t)BI * LI * DI;

    bf16 *qhi,*qlo,*khi,*klo,*vhi,*vlo,*wqh,*wql,*wkh,*wkl,*wvh,*wvl,*woh,*wol;
    bf16 *Qhi,*Qlo,*Khi,*Klo,*VHh,*VHl,*Vth,*Vtl,*Ohi,*Olo;
    float* O2;
    cudaGetSymbolAddress((void**)&qhi, g_qhi);  cudaGetSymbolAddress((void**)&qlo, g_qlo);
    cudaGetSymbolAddress((void**)&khi, g_khi);  cudaGetSymbolAddress((void**)&klo, g_klo);
    cudaGetSymbolAddress((void**)&vhi, g_vhi);  cudaGetSymbolAddress((void**)&vlo, g_vlo);
    cudaGetSymbolAddress((void**)&wqh, g_wqhi); cudaGetSymbolAddress((void**)&wql, g_wqlo);
    cudaGetSymbolAddress((void**)&wkh, g_wkhi); cudaGetSymbolAddress((void**)&wkl, g_wklo);
    cudaGetSymbolAddress((void**)&wvh, g_wvhi); cudaGetSymbolAddress((void**)&wvl, g_wvlo);
    cudaGetSymbolAddress((void**)&woh, g_wohi); cudaGetSymbolAddress((void**)&wol, g_wolo);
    cudaGetSymbolAddress((void**)&Qhi, g_Qhi);  cudaGetSymbolAddress((void**)&Qlo, g_Qlo);
    cudaGetSymbolAddress((void**)&Khi, g_Khi);  cudaGetSymbolAddress((void**)&Klo, g_Klo);
    cudaGetSymbolAddress((void**)&VHh, g_VHhi); cudaGetSymbolAddress((void**)&VHl, g_VHlo);
    cudaGetSymbolAddress((void**)&Vth, g_Vthi); cudaGetSymbolAddress((void**)&Vtl, g_Vtlo);
    cudaGetSymbolAddress((void**)&Ohi, g_Ohi);  cudaGetSymbolAddress((void**)&Olo, g_Olo);
    cudaGetSymbolAddress((void**)&O2,  g_O2);

    // smem: MODE0/1/2 (BN=128): 2*(2*10240+2*10240) = 81920; MODE3 (BN=64): 61440
    const int SM128 = 81920, SM64 = 61440;
    cudaFuncSetAttribute(gemm_mma<128,0>, cudaFuncAttributeMaxDynamicSharedMemorySize, SM128);
    cudaFuncSetAttribute(gemm_mma<128,1>, cudaFuncAttributeMaxDynamicSharedMemorySize, SM128);
    cudaFuncSetAttribute(gemm_mma<128,2>, cudaFuncAttributeMaxDynamicSharedMemorySize, SM128);
    cudaFuncSetAttribute(gemm_mma<64,3>,  cudaFuncAttributeMaxDynamicSharedMemorySize, SM64);

    // input/weight splits
    convert_split<<<8192, 256>>>(q, qhi, qlo, 2097152);
    convert_split<<<8192, 256>>>(k, khi, klo, 2097152);
    convert_split<<<8192, 256>>>(v, vhi, vlo, 2097152);
    convert_split<<<1024, 256>>>(Wq, wqh, wql, 262144);
    convert_split<<<1024, 256>>>(Wk, wkh, wkl, 262144);
    convert_split<<<1024, 256>>>(Wv, wvh, wvl, 262144);
    convert_split<<<1024, 256>>>(Wo, woh, wol, 262144);

    // QKV projections -> per-head split layouts
    gemm_mma<128,0><<<dim3(8,64,1), 256, SM128>>>(qhi,qlo,nullptr, wqh,wql, nullptr,Qhi,Qlo, bq, DI);
    gemm_mma<128,0><<<dim3(8,64,1), 256, SM128>>>(khi,klo,nullptr, wkh,wkl, nullptr,Khi,Klo, bk, DI);
    gemm_mma<128,0><<<dim3(8,64,1), 256, SM128>>>(vhi,vlo,nullptr, wvh,wvl, nullptr,VHh,VHl, bv, DI);

    // V transpose
    transpose_bf<<<dim3(2,64,64), dim3(32,8)>>>(VHh, VHl, Vth, Vtl);

    // scores (+scale, diag mask) -> attn_flat, then softmax in place
    gemm_mma<128,2><<<dim3(16,16,64), 256, SM128>>>(Qhi,Qlo,nullptr, Khi,Klo, attn,nullptr,nullptr, nullptr, 64);
    softmax_kernel<<<BI*HI*LI, 256>>>(attn);

    // attn @ V
    gemm_mma<64,3><<<dim3(1,16,64), 256, SM64>>>(nullptr,nullptr,attn, Vth,Vtl, nullptr,Ohi,Olo, nullptr, LI);

    // output projection + residual/LN
    gemm_mma<128,1><<<dim3(8,64,1), 256, SM128>>>(Ohi,Olo,nullptr, woh,wol, O2,nullptr,nullptr, bo, DI);
    ln_kernel<<<BI*LI, 256>>>(O2, q, gamma, beta, out);
}

// round 5
// speedup vs baseline: 2.5829x; 1.1422x over previous
#include <cuda_runtime.h>
#include <cuda_bf16.h>
#include <cstdint>
#include <math.h>

#define BI 4
#define LI 2048
#define DI 1024
#define HI 16

typedef __nv_bfloat16 bf16;
#define ELI ((size_t)8192*1024)
#define ELW ((size_t)1024*1024)

// device-global scratch (allocation-free rule)
__device__ __align__(256) bf16 g_qhi[ELI], g_qlo[ELI], g_khi[ELI], g_klo[ELI], g_vhi[ELI], g_vlo[ELI];
__device__ __align__(256) bf16 g_wqhi[ELW], g_wqlo[ELW], g_wkhi[ELW], g_wklo[ELW];
__device__ __align__(256) bf16 g_wvhi[ELW], g_wvlo[ELW], g_wohi[ELW], g_wolo[ELW];
__device__ __align__(256) bf16 g_Qhi[ELI], g_Qlo[ELI], g_Khi[ELI], g_Klo[ELI];   // [bh][l][64]
__device__ __align__(256) bf16 g_VHhi[ELI], g_VHlo[ELI];                         // [bh][l][64]
__device__ __align__(256) bf16 g_Vthi[ELI], g_Vtlo[ELI];                         // [bh][64][2048]
__device__ __align__(256) bf16 g_Ohi[ELI], g_Olo[ELI];                           // [8192][1024]
__device__ __align__(256) float g_O2[ELI];
// softmax stats: per (z,row) 16 tile maxima / sums; combined M and 1/S
__device__ __align__(256) float g_tm[(size_t)64*2048*16], g_ts[(size_t)64*2048*16];
__device__ __align__(256) float g_M[(size_t)64*2048], g_I[(size_t)64*2048];

// ---------------- helpers ----------------
__device__ __forceinline__ uint32_t s2u(const void* p) {
    uint32_t a;
    asm("{ .reg .u64 t; cvta.to.shared.u64 t, %1; cvt.u32.u64 %0, t; }" : "=r"(a) : "l"(p));
    return a;
}
__device__ __forceinline__ void ldm4(uint32_t* r, uint32_t a) {
    asm volatile("ldmatrix.sync.aligned.m8n8.x4.shared.b16 {%0,%1,%2,%3}, [%4];"
                 : "=r"(r[0]), "=r"(r[1]), "=r"(r[2]), "=r"(r[3]) : "r"(a));
}
__device__ __forceinline__ void mma16816(float* c, const uint32_t* a, const uint32_t* b) {
    asm volatile("mma.sync.aligned.m16n8k16.row.col.f32.bf16.bf16.f32 "
                 "{%0,%1,%2,%3}, {%4,%5,%6,%7}, {%8,%9}, {%0,%1,%2,%3};"
                 : "+f"(c[0]), "+f"(c[1]), "+f"(c[2]), "+f"(c[3])
                 : "r"(a[0]), "r"(a[1]), "r"(a[2]), "r"(a[3]), "r"(b[0]), "r"(b[1]));
}
#define CP16(d, s)  asm volatile("cp.async.cg.shared.global [%0], [%1], 16;" :: "r"(d), "l"(s))
#define CP_COMMIT() asm volatile("cp.async.commit_group;")
#define CP_WAIT1()  asm volatile("cp.async.wait_group 1;")

__device__ __forceinline__ void split2(float x0, float x1, unsigned& H, unsigned& L) {
    bf16 h0 = __float2bfloat16(x0), h1 = __float2bfloat16(x1);
    bf16 l0 = __float2bfloat16(x0 - __bfloat162float(h0));
    bf16 l1 = __float2bfloat16(x1 - __bfloat162float(h1));
    H = (unsigned)__bfloat16_as_ushort(h0) | ((unsigned)__bfloat16_as_ushort(h1) << 16);
    L = (unsigned)__bfloat16_as_ushort(l0) | ((unsigned)__bfloat16_as_ushort(l1) << 16);
}

struct CvtSet { const float* s[4]; bf16* h[4]; bf16* l[4]; int n4; };
__global__ void __launch_bounds__(256) convert_multi(CvtSet p) {
    int y = blockIdx.y;
    int i = blockIdx.x * 256 + threadIdx.x;
    if (i >= p.n4) return;
    float4 v = ((const float4*)p.s[y])[i];
    unsigned h01, l01, h23, l23;
    split2(v.x, v.y, h01, l01); split2(v.z, v.w, h23, l23);
    ((uint2*)p.h[y])[i] = make_uint2(h01, h23);
    ((uint2*)p.l[y])[i] = make_uint2(l01, l23);
}

// ---------------------------------------------------------------------------
// mma.sync split-bf16 GEMM: C = A(MxK,row) * B(NxK,row)^T, CTA tile 128 x BN
// MODE 0: QKV proj -> Chi/Clo scatter [bh][l][64], +bias
// MODE 1: out proj -> Cf [8192][1024], +bias
// MODE 2: scores   -> Cf attn (scaled, diag=-inf) + per-tile softmax stats
// MODE 3: attn@V   -> Cf = attn (read raw, exp-normalize via gM/gI, write back
//                    final attn in place, split to bf16, MMA) -> Chi/Clo
// ---------------------------------------------------------------------------
template<int BN, int MODE>
__global__ void __launch_bounds__(256)
gemm_mma(const bf16* __restrict__ Ahi, const bf16* __restrict__ Alo,
         const bf16* __restrict__ Bhi, const bf16* __restrict__ Blo,
         float* __restrict__ Cf, bf16* __restrict__ Chi, bf16* __restrict__ Clo,
         const float* __restrict__ bias,
         const float* __restrict__ gM, const float* __restrict__ gI,
         float* __restrict__ gtm, float* __restrict__ gts, int K)
{
    constexpr int BM = 128, BK = 32, BKP = 40;
    constexpr int ASZ = BM * BKP * 2;            // bytes per A plane
    constexpr int BSZ = BN * BKP * 2;
    constexpr int STAGE = 2 * ASZ + 2 * BSZ;
    constexpr int NF = BN / 16;
    constexpr int BV = BN / 64;                  // 16B cp per thread per B plane

    extern __shared__ char smem[];
    const uint32_t sbase = s2u(smem);
    __shared__ float sM[128], sI[128];
    __shared__ float sm_m[2][128], sm_s[2][128];

    const int t = threadIdx.x, l = t & 31, wid = t >> 5;
    const int wm = wid & 3, wn = wid >> 2;
    const int gid = l >> 2, tig = l & 3;
    const int bc = blockIdx.x, br = blockIdx.y, z = blockIdx.z;

    const bf16 *Ah = Ahi, *Al = Alo, *Bh = Bhi, *Bl = Blo;
    float* Aw = nullptr;    // MODE3: writable attn
    if (MODE == 2) { size_t o = (size_t)z * LI * 64; Ah += o; Al += o; Bh += o; Bl += o; }
    if (MODE == 3) {
        Aw = Cf + ((size_t)((z & 15) * BI + (z >> 4))) * LI * LI;
        size_t o = (size_t)z * 64 * LI; Bh += o; Bl += o;
        if (t < 128) {
            size_t r = (size_t)z * LI + br * 128 + t;
            sM[t] = gM[r]; sI[t] = gI[r];
        }
        __syncthreads();
    }

    // fragment smem offsets
    int aoff[2], boff[NF / 2];
    #pragma unroll
    for (int mi = 0; mi < 2; mi++)
        aoff[mi] = ((wm * 32 + mi * 16 + (l & 15)) * BKP + ((l & 16) >> 1)) * 2;
    #pragma unroll
    for (int p = 0; p < NF / 2; p++)
        boff[p] = ((wn * (BN / 2) + p * 16 + (l & 7) + ((l >> 1) & 8)) * BKP + (l & 8)) * 2;

    float acc[2][NF][4];
    #pragma unroll
    for (int mi = 0; mi < 2; mi++)
        #pragma unroll
        for (int ni = 0; ni < NF; ni++)
            #pragma unroll
            for (int c = 0; c < 4; c++) acc[mi][ni][c] = 0.f;

    const int n = K / BK;
    float4 raf[4];   // MODE3 A staging

    // async issue: A (bf16 modes) + B planes
    auto issue_async = [&](int ck) {
        int k0 = ck * BK;
        uint32_t sd = sbase + (ck & 1) * STAGE;
        if (MODE != 3) {
            #pragma unroll
            for (int i = 0; i < 2; i++) {
                int vi = t + i * 256, row = vi >> 2, kc = (vi & 3) * 8;
                uint32_t off = (uint32_t)(row * BKP + kc) * 2;
                size_t g = (size_t)(br * 128 + row) * K + k0 + kc;
                CP16(sd + off,       Ah + g);
                CP16(sd + ASZ + off, Al + g);
            }
        }
        #pragma unroll
        for (int i = 0; i < BV; i++) {
            int vi = t + i * 256, row = vi >> 2, kc = (vi & 3) * 8;
            uint32_t off = (uint32_t)(row * BKP + kc) * 2;
            size_t g = (size_t)(bc * BN + row) * K + k0 + kc;
            CP16(sd + 2 * ASZ + off,       Bh + g);
            CP16(sd + 2 * ASZ + BSZ + off, Bl + g);
        }
    };
    auto ldg_regs = [&](int ck) {    // MODE3 only
        int k0 = ck * BK;
        #pragma unroll
        for (int i = 0; i < 4; i++) {
            int vi = t + i * 256, row = vi >> 3, kc = (vi & 7) * 4;
            raf[i] = *(const float4*)(Aw + (size_t)(br * 128 + row) * K + k0 + kc);
        }
    };
    auto proc_sts = [&](int ck) {    // MODE3 only: exp-normalize, write attn, split, sts
        int k0 = ck * BK;
        char* st = smem + (ck & 1) * STAGE;
        #pragma unroll
        for (int i = 0; i < 4; i++) {
            int vi = t + i * 256, row = vi >> 3, kc = (vi & 7) * 4;
            float M = sM[row], I = sI[row];
            float4 v = raf[i];
            v.x = __expf(v.x - M) * I; v.y = __expf(v.y - M) * I;
            v.z = __expf(v.z - M) * I; v.w = __expf(v.w - M) * I;
            *(float4*)(Aw + (size_t)(br * 128 + row) * K + k0 + kc) = v;
            unsigned h01, l01, h23, l23;
            split2(v.x, v.y, h01, l01); split2(v.z, v.w, h23, l23);
            *(uint2*)(st + (row * BKP + kc) * 2)       = make_uint2(h01, h23);
            *(uint2*)(st + ASZ + (row * BKP + kc) * 2) = make_uint2(l01, l23);
        }
    };
    auto compute = [&](int buf) {
        uint32_t sb = sbase + buf * STAGE;
        #pragma unroll
        for (int ks = 0; ks < 2; ks++) {
            int kb = ks * 32;
            uint32_t ah[2][4], al[2][4];
            #pragma unroll
            for (int mi = 0; mi < 2; mi++) {
                ldm4(ah[mi], sb + aoff[mi] + kb);
                ldm4(al[mi], sb + ASZ + aoff[mi] + kb);
            }
            uint32_t bh[NF][2], bl[NF][2];
            #pragma unroll
            for (int p = 0; p < NF / 2; p++) {
                uint32_t r[4];
                ldm4(r, sb + 2 * ASZ + boff[p] + kb);
                bh[2*p][0] = r[0]; bh[2*p][1] = r[1]; bh[2*p+1][0] = r[2]; bh[2*p+1][1] = r[3];
                ldm4(r, sb + 2 * ASZ + BSZ + boff[p] + kb);
                bl[2*p][0] = r[0]; bl[2*p][1] = r[1]; bl[2*p+1][0] = r[2]; bl[2*p+1][1] = r[3];
            }
            #pragma unroll
            for (int mi = 0; mi < 2; mi++)
                #pragma unroll
                for (int ni = 0; ni < NF; ni++) {
                    mma16816(acc[mi][ni], ah[mi], bh[ni]);
                    mma16816(acc[mi][ni], ah[mi], bl[ni]);
                    mma16816(acc[mi][ni], al[mi], bh[ni]);
                }
        }
    };

    // ---- pipeline ----
    if (MODE == 3) { ldg_regs(0); issue_async(0); proc_sts(0); }
    else           { issue_async(0); }
    CP_COMMIT();
    for (int ck = 0; ck < n; ck++) {
        if (ck + 1 < n) { issue_async(ck + 1); if (MODE == 3) ldg_regs(ck + 1); }
        CP_COMMIT();
        CP_WAIT1();
        __syncthreads();
        compute(ck & 1);
        __syncthreads();
        if (MODE == 3 && ck + 1 < n) proc_sts(ck + 1);
    }

    // ---- MODE2: scale + mask in place ----
    if (MODE == 2) {
        #pragma unroll
        for (int mi = 0; mi < 2; mi++)
            #pragma unroll
            for (int ni = 0; ni < NF; ni++)
                #pragma unroll
                for (int c = 0; c < 4; c++) {
                    int gi = br * 128 + wm * 32 + mi * 16 + gid + (c >> 1) * 8;
                    int gj = bc * BN + wn * (BN / 2) + ni * 8 + tig * 2 + (c & 1);
                    float v = acc[mi][ni][c] * 0.125f;
                    if (gi == gj) v = -INFINITY;
                    acc[mi][ni][c] = v;
                }
    }

    // ---- epilogue writes ----
    #pragma unroll
    for (int mi = 0; mi < 2; mi++)
        #pragma unroll
        for (int ni = 0; ni < NF; ni++)
            #pragma unroll
            for (int h = 0; h < 2; h++) {
                int gi = br * 128 + wm * 32 + mi * 16 + gid + h * 8;
                int gj = bc * BN + wn * (BN / 2) + ni * 8 + tig * 2;
                float v0 = acc[mi][ni][h * 2 + 0];
                float v1 = acc[mi][ni][h * 2 + 1];
                if (MODE == 1) {
                    v0 += bias[gj]; v1 += bias[gj + 1];
                    *(float2*)&Cf[(size_t)gi * DI + gj] = make_float2(v0, v1);
                } else if (MODE == 0) {
                    v0 += bias[gj]; v1 += bias[gj + 1];
                    unsigned H, L;
                    split2(v0, v1, H, L);
                    size_t e = (((size_t)((gi >> 11) * HI + (gj >> 6)) * LI + (gi & 2047)) << 6) + (gj & 63);
                    ((unsigned*)Chi)[e >> 1] = H;
                    ((unsigned*)Clo)[e >> 1] = L;
                } else if (MODE == 2) {
                    int b = z >> 4, hh = z & 15;
                    *(float2*)&Cf[((size_t)(hh * BI + b) * LI + gi) * LI + gj] = make_float2(v0, v1);
                } else { // MODE 3
                    unsigned H, L;
                    split2(v0, v1, H, L);
                    size_t e = ((size_t)(z >> 4) * LI + gi) * DI + (z & 15) * 64 + gj;
                    ((unsigned*)Chi)[e >> 1] = H;
                    ((unsigned*)Clo)[e >> 1] = L;
                }
            }

    // ---- MODE2: per-tile softmax stats ----
    if (MODE == 2) {
        #pragma unroll
        for (int mi = 0; mi < 2; mi++)
            #pragma unroll
            for (int h = 0; h < 2; h++) {
                float m = -INFINITY;
                #pragma unroll
                for (int ni = 0; ni < NF; ni++) {
                    m = fmaxf(m, acc[mi][ni][h * 2 + 0]);
                    m = fmaxf(m, acc[mi][ni][h * 2 + 1]);
                }
                m = fmaxf(m, __shfl_xor_sync(0xffffffffu, m, 1));
                m = fmaxf(m, __shfl_xor_sync(0xffffffffu, m, 2));
                float s = 0.f;
                #pragma unroll
                for (int ni = 0; ni < NF; ni++) {
                    s += __expf(acc[mi][ni][h * 2 + 0] - m);
                    s += __expf(acc[mi][ni][h * 2 + 1] - m);
                }
                s += __shfl_xor_sync(0xffffffffu, s, 1);
                s += __shfl_xor_sync(0xffffffffu, s, 2);
                int rl = wm * 32 + mi * 16 + h * 8 + gid;
                if (tig == 0) { sm_m[wn][rl] = m; sm_s[wn][rl] = s; }
            }
        __syncthreads();
        if (t < 128) {
            float m0 = sm_m[0][t], m1 = sm_m[1][t];
            float s0 = sm_s[0][t], s1 = sm_s[1][t];
            float m = fmaxf(m0, m1);
            float s = s0 * __expf(m0 - m) + s1 * __expf(m1 - m);
            size_t o = ((size_t)z * LI + br * 128 + t) * 16 + bc;
            gtm[o] = m; gts[o] = s;
        }
    }
}

// combine per-tile stats -> row M, 1/S
__global__ void __launch_bounds__(256) combine_stats(const float* __restrict__ tm,
                                                     const float* __restrict__ ts,
                                                     float* __restrict__ M, float* __restrict__ I) {
    size_t r = blockIdx.x * 256 + threadIdx.x;
    const float* pm = tm + r * 16;
    const float* ps = ts + r * 16;
    float m = -INFINITY;
    #pragma unroll
    for (int i = 0; i < 16; i++) m = fmaxf(m, pm[i]);
    float s = 0.f;
    #pragma unroll
    for (int i = 0; i < 16; i++) s += ps[i] * __expf(pm[i] - m);
    M[r] = m; I[r] = 1.f / s;
}

// ---------------- V transpose (hi+lo): [bh][l][64] -> [bh][64][2048] ----------
__global__ void __launch_bounds__(256) transpose_bf(const bf16* __restrict__ ih, const bf16* __restrict__ il,
                                                    bf16* __restrict__ oh, bf16* __restrict__ ol) {
    __shared__ bf16 th[32][33], tl[32][33];
    int z = blockIdx.z, l0 = blockIdx.y * 32, d0 = blockIdx.x * 32;
    int x = threadIdx.x, y = threadIdx.y;
    #pragma unroll
    for (int i = 0; i < 32; i += 8) {
        size_t g = ((size_t)z * LI + l0 + y + i) * 64 + d0 + x;
        th[y + i][x] = ih[g]; tl[y + i][x] = il[g];
    }
    __syncthreads();
    #pragma unroll
    for (int i = 0; i < 32; i += 8) {
        size_t g = ((size_t)z * 64 + d0 + y + i) * LI + l0 + x;
        oh[g] = th[x][y + i]; ol[g] = tl[x][y + i];
    }
}

// ---------------- residual + LayerNorm ----------------
__device__ __forceinline__ float warpSum(float v) {
    #pragma unroll
    for (int o = 16; o; o >>= 1) v += __shfl_xor_sync(0xffffffffu, v, o);
    return v;
}
__global__ void __launch_bounds__(256) ln_kernel(const float* __restrict__ o2, const float* __restrict__ res,
                                                 const float* __restrict__ gamma, const float* __restrict__ beta,
                                                 float* __restrict__ out) {
    size_t row = blockIdx.x;
    int t = threadIdx.x;
    float4 a = ((const float4*)(o2 + row * DI))[t];
    float4 r = ((const float4*)(res + row * DI))[t];
    float x0 = a.x + r.x, x1 = a.y + r.y, x2 = a.z + r.z, x3 = a.w + r.w;
    float s = x0 + x1 + x2 + x3, sq = x0 * x0 + x1 * x1 + x2 * x2 + x3 * x3;
    s = warpSum(s); sq = warpSum(sq);
    __shared__ float rs[8], rq[8];
    if ((t & 31) == 0) { rs[t >> 5] = s; rq[t >> 5] = sq; }
    __syncthreads();
    s = 0.f; sq = 0.f;
    #pragma unroll
    for (int i = 0; i < 8; i++) { s += rs[i]; sq += rq[i]; }
    float mu = s * (1.0f / DI);
    float rstd = rsqrtf(sq * (1.0f / DI) - mu * mu + 1e-5f);
    float4 g = ((const float4*)gamma)[t], b = ((const float4*)beta)[t];
    float4 o;
    o.x = (x0 - mu) * rstd * g.x + b.x; o.y = (x1 - mu) * rstd * g.y + b.y;
    o.z = (x2 - mu) * rstd * g.z + b.z; o.w = (x3 - mu) * rstd * g.w + b.w;
    ((float4*)(out + row * DI))[t] = o;
}

// ---------------------------------------------------------------------------
extern "C" void kernel_launch(void* const* d_in, const int* in_sizes, int n_in,
                              void* d_out, int out_size)
{
    const float* q  = (const float*)d_in[0];
    const float* k  = (const float*)d_in[1];
    const float* v  = (const float*)d_in[2];
    const float* Wq = (const float*)d_in[3];  const float* bq = (const float*)d_in[4];
    const float* Wk = (const float*)d_in[5];  const float* bk = (const float*)d_in[6];
    const float* Wv = (const float*)d_in[7];  const float* bv = (const float*)d_in[8];
    const float* Wo = (const float*)d_in[9];  const float* bo = (const float*)d_in[10];
    const float* gamma = (const float*)d_in[11];
    const float* beta  = (const float*)d_in[12];

    float* out  = (float*)d_out;
    float* attn = out + (size_t)BI * LI * DI;

    bf16 *qhi,*qlo,*khi,*klo,*vhi,*vlo,*wqh,*wql,*wkh,*wkl,*wvh,*wvl,*woh,*wol;
    bf16 *Qhi,*Qlo,*Khi,*Klo,*VHh,*VHl,*Vth,*Vtl,*Ohi,*Olo;
    float *O2, *tm, *ts, *M, *I;
    cudaGetSymbolAddress((void**)&qhi, g_qhi);  cudaGetSymbolAddress((void**)&qlo, g_qlo);
    cudaGetSymbolAddress((void**)&khi, g_khi);  cudaGetSymbolAddress((void**)&klo, g_klo);
    cudaGetSymbolAddress((void**)&vhi, g_vhi);  cudaGetSymbolAddress((void**)&vlo, g_vlo);
    cudaGetSymbolAddress((void**)&wqh, g_wqhi); cudaGetSymbolAddress((void**)&wql, g_wqlo);
    cudaGetSymbolAddress((void**)&wkh, g_wkhi); cudaGetSymbolAddress((void**)&wkl, g_wklo);
    cudaGetSymbolAddress((void**)&wvh, g_wvhi); cudaGetSymbolAddress((void**)&wvl, g_wvlo);
    cudaGetSymbolAddress((void**)&woh, g_wohi); cudaGetSymbolAddress((void**)&wol, g_wolo);
    cudaGetSymbolAddress((void**)&Qhi, g_Qhi);  cudaGetSymbolAddress((void**)&Qlo, g_Qlo);
    cudaGetSymbolAddress((void**)&Khi, g_Khi);  cudaGetSymbolAddress((void**)&Klo, g_Klo);
    cudaGetSymbolAddress((void**)&VHh, g_VHhi); cudaGetSymbolAddress((void**)&VHl, g_VHlo);
    cudaGetSymbolAddress((void**)&Vth, g_Vthi); cudaGetSymbolAddress((void**)&Vtl, g_Vtlo);
    cudaGetSymbolAddress((void**)&Ohi, g_Ohi);  cudaGetSymbolAddress((void**)&Olo, g_Olo);
    cudaGetSymbolAddress((void**)&O2,  g_O2);
    cudaGetSymbolAddress((void**)&tm,  g_tm);   cudaGetSymbolAddress((void**)&ts,  g_ts);
    cudaGetSymbolAddress((void**)&M,   g_M);    cudaGetSymbolAddress((void**)&I,   g_I);

    const int SM128 = 81920, SM64 = 61440;
    cudaFuncSetAttribute(gemm_mma<128,0>, cudaFuncAttributeMaxDynamicSharedMemorySize, SM128);
    cudaFuncSetAttribute(gemm_mma<128,1>, cudaFuncAttributeMaxDynamicSharedMemorySize, SM128);
    cudaFuncSetAttribute(gemm_mma<128,2>, cudaFuncAttributeMaxDynamicSharedMemorySize, SM128);
    cudaFuncSetAttribute(gemm_mma<64,3>,  cudaFuncAttributeMaxDynamicSharedMemorySize, SM64);

    // input/weight splits (2 launches)
    CvtSet ci; ci.s[0]=q; ci.s[1]=k; ci.s[2]=v; ci.s[3]=q;
    ci.h[0]=qhi; ci.h[1]=khi; ci.h[2]=vhi; ci.h[3]=qhi;
    ci.l[0]=qlo; ci.l[1]=klo; ci.l[2]=vlo; ci.l[3]=qlo;
    ci.n4 = 2097152;
    convert_multi<<<dim3(8192,3), 256>>>(ci);
    CvtSet cw; cw.s[0]=Wq; cw.s[1]=Wk; cw.s[2]=Wv; cw.s[3]=Wo;
    cw.h[0]=wqh; cw.h[1]=wkh; cw.h[2]=wvh; cw.h[3]=woh;
    cw.l[0]=wql; cw.l[1]=wkl; cw.l[2]=wvl; cw.l[3]=wol;
    cw.n4 = 262144;
    convert_multi<<<dim3(1024,4), 256>>>(cw);

    // QKV projections
    gemm_mma<128,0><<<dim3(8,64,1), 256, SM128>>>(qhi,qlo, wqh,wql, nullptr,Qhi,Qlo, bq, nullptr,nullptr,nullptr,nullptr, DI);
    gemm_mma<128,0><<<dim3(8,64,1), 256, SM128>>>(khi,klo, wkh,wkl, nullptr,Khi,Klo, bk, nullptr,nullptr,nullptr,nullptr, DI);
    gemm_mma<128,0><<<dim3(8,64,1), 256, SM128>>>(vhi,vlo, wvh,wvl, nullptr,VHh,VHl, bv, nullptr,nullptr,nullptr,nullptr, DI);

    // V transpose
    transpose_bf<<<dim3(2,64,64), dim3(32,8)>>>(VHh, VHl, Vth, Vtl);

    // scores (+scale, diag mask, per-tile stats) -> attn buffer
    gemm_mma<128,2><<<dim3(16,16,64), 256, SM128>>>(Qhi,Qlo, Khi,Klo, attn,nullptr,nullptr, nullptr, nullptr,nullptr,tm,ts, 64);

    // combine stats -> row M, 1/S
    combine_stats<<<512, 256>>>(tm, ts, M, I);

    // fused softmax-normalize + attn write + attn @ V
    gemm_mma<64,3><<<dim3(1,16,64), 256, SM64>>>(nullptr,nullptr, Vth,Vtl, attn,Ohi,Olo, nullptr, M,I,nullptr,nullptr, LI);

    // output projection + residual/LN
    gemm_mma<128,1><<<dim3(8,64,1), 256, SM128>>>(Ohi,Olo, woh,wol, O2,nullptr,nullptr, bo, nullptr,nullptr,nullptr,nullptr, DI);
    ln_kernel<<<BI*LI, 256>>>(O2, q, gamma, beta, out);
}